// round 2
// baseline (speedup 1.0000x reference)
#include <cuda_runtime.h>
#include <cuda_bf16.h>

#define N_NODES 50000
#define N_EDGES 800000
#define LATDIM  128

typedef unsigned long long ull;

// ---- scratch (static device globals: the sanctioned no-alloc workaround) ----
__device__ float g_Q[N_NODES * LATDIM];
__device__ float g_K[N_NODES * LATDIM];
__device__ float g_V[N_NODES * LATDIM];
__device__ int   g_cnt[N_NODES];
__device__ int   g_rowptr[N_NODES + 1];
__device__ int   g_fill[N_NODES];
__device__ int   g_adj[N_EDGES];

// ---- packed f32x2 helpers (FFMA2 path, sm_103a) ----
__device__ __forceinline__ ull pack2(float lo, float hi) {
    ull r;
    asm("mov.b64 %0, {%1, %2};" : "=l"(r)
        : "r"(__float_as_uint(lo)), "r"(__float_as_uint(hi)));
    return r;
}
__device__ __forceinline__ void fma2(ull& d, ull a, ull b) {
    asm("fma.rn.f32x2 %0, %1, %2, %3;" : "=l"(d) : "l"(a), "l"(b), "l"(d));
}
__device__ __forceinline__ void unpack2(ull v, float& lo, float& hi) {
    unsigned ulo, uhi;
    asm("mov.b64 {%0, %1}, %2;" : "=r"(ulo), "=r"(uhi) : "l"(v));
    lo = __uint_as_float(ulo);
    hi = __uint_as_float(uhi);
}

// ============================================================
// Kernel 1: fused Q/K/V projection. grid = (ceil(N/128), 3).
// Block 256 threads, each computes 8 rows x 8 cols using f32x2 FMAs.
// ============================================================
__global__ __launch_bounds__(256, 2)
void gemm3_kernel(const float* __restrict__ E,
                  const float* __restrict__ qW,
                  const float* __restrict__ kW,
                  const float* __restrict__ vW,
                  int N)
{
    __shared__ float As[32][132];   // A tile transposed: As[k][row]
    __shared__ float Bs[32][128];   // W tile: Bs[k][col]

    const float* W   = (blockIdx.y == 0) ? qW : (blockIdx.y == 1 ? kW : vW);
    float*       Out = (blockIdx.y == 0) ? g_Q : (blockIdx.y == 1 ? g_K : g_V);

    const int row0 = blockIdx.x * 128;
    const int tid  = threadIdx.x;
    const int tr   = (tid >> 4) << 3;   // thread row base (0..120)
    const int tc   = (tid & 15) << 3;   // thread col base (0..120)

    ull acc[8][4];
#pragma unroll
    for (int i = 0; i < 8; i++)
#pragma unroll
        for (int j = 0; j < 4; j++) acc[i][j] = 0ULL;

    for (int kc = 0; kc < LATDIM; kc += 32) {
        // load W chunk (32 x 128) into Bs
#pragma unroll
        for (int v = tid; v < 32 * 32; v += 256) {
            int k = v >> 5, c4 = v & 31;
            *(float4*)&Bs[k][c4 * 4] =
                __ldg((const float4*)(W + (size_t)(kc + k) * LATDIM) + c4);
        }
        // load A chunk (128 rows x 32 k) transposed into As
        {
            int kq = (tid & 7) * 4;
            int rb = tid >> 3;
#pragma unroll
            for (int rr = 0; rr < 4; rr++) {
                int r = rb + rr * 32;
                int grow = row0 + r;
                float4 a = (grow < N)
                    ? __ldg((const float4*)(E + (size_t)grow * LATDIM + kc + kq))
                    : make_float4(0.f, 0.f, 0.f, 0.f);
                As[kq + 0][r] = a.x;
                As[kq + 1][r] = a.y;
                As[kq + 2][r] = a.z;
                As[kq + 3][r] = a.w;
            }
        }
        __syncthreads();

#pragma unroll 8
        for (int k = 0; k < 32; k++) {
            float4 a0 = *(const float4*)&As[k][tr];
            float4 a1 = *(const float4*)&As[k][tr + 4];
            ulonglong2 bq0 = *(const ulonglong2*)&Bs[k][tc];
            ulonglong2 bq1 = *(const ulonglong2*)&Bs[k][tc + 4];
            ull bb[4] = {bq0.x, bq0.y, bq1.x, bq1.y};
            ull aa[8];
            aa[0] = pack2(a0.x, a0.x); aa[1] = pack2(a0.y, a0.y);
            aa[2] = pack2(a0.z, a0.z); aa[3] = pack2(a0.w, a0.w);
            aa[4] = pack2(a1.x, a1.x); aa[5] = pack2(a1.y, a1.y);
            aa[6] = pack2(a1.z, a1.z); aa[7] = pack2(a1.w, a1.w);
#pragma unroll
            for (int i = 0; i < 8; i++) {
                fma2(acc[i][0], aa[i], bb[0]);
                fma2(acc[i][1], aa[i], bb[1]);
                fma2(acc[i][2], aa[i], bb[2]);
                fma2(acc[i][3], aa[i], bb[3]);
            }
        }
        __syncthreads();
    }

#pragma unroll
    for (int i = 0; i < 8; i++) {
        int grow = row0 + tr + i;
        if (grow < N) {
            float o[8];
#pragma unroll
            for (int j = 0; j < 4; j++) unpack2(acc[i][j], o[2 * j], o[2 * j + 1]);
            *(float4*)(Out + (size_t)grow * LATDIM + tc)     = make_float4(o[0], o[1], o[2], o[3]);
            *(float4*)(Out + (size_t)grow * LATDIM + tc + 4) = make_float4(o[4], o[5], o[6], o[7]);
        }
    }
}

// ============================================================
// CSR build: zero -> histogram -> scan -> scatter
// ============================================================
__global__ void zero_kernel(int n) {
    int i = blockIdx.x * blockDim.x + threadIdx.x;
    if (i < n) g_cnt[i] = 0;
}

__global__ void hist_kernel(const int* __restrict__ rows, int nE) {
    int e = blockIdx.x * blockDim.x + threadIdx.x;
    if (e < nE) atomicAdd(&g_cnt[rows[e]], 1);
}

// ============================================================
// Single-block exclusive scan, 2 barriers total.
// Each thread owns a contiguous chunk of ITEMS elements:
//   pass 1: chunk sum; warp-shuffle scan over 1024 thread sums;
//   pass 2: replay chunk writing running exclusive prefixes.
// ============================================================
#define SCAN_THREADS 1024
#define SCAN_ITEMS   ((N_NODES + SCAN_THREADS - 1) / SCAN_THREADS)  // 49

__global__ __launch_bounds__(SCAN_THREADS)
void scan_kernel(int n) {
    __shared__ int warp_sums[32];

    const int tid  = threadIdx.x;
    const int lane = tid & 31;
    const int wid  = tid >> 5;
    const int base = tid * SCAN_ITEMS;

    // pass 1: chunk sum
    int sum = 0;
#pragma unroll 7
    for (int i = 0; i < SCAN_ITEMS; i++) {
        int idx = base + i;
        if (idx < n) sum += g_cnt[idx];
    }

    // inclusive warp scan of thread sums
    int s = sum;
#pragma unroll
    for (int o = 1; o < 32; o <<= 1) {
        int t = __shfl_up_sync(0xffffffffu, s, o);
        if (lane >= o) s += t;
    }
    if (lane == 31) warp_sums[wid] = s;
    __syncthreads();

    // warp 0 scans the 32 warp totals (inclusive)
    if (wid == 0) {
        int w = warp_sums[lane];
#pragma unroll
        for (int o = 1; o < 32; o <<= 1) {
            int t = __shfl_up_sync(0xffffffffu, w, o);
            if (lane >= o) w += t;
        }
        warp_sums[lane] = w;
    }
    __syncthreads();

    // global exclusive prefix for this thread's chunk
    int excl = (s - sum) + (wid > 0 ? warp_sums[wid - 1] : 0);

    // pass 2: replay chunk, writing running prefixes
    int run = excl;
#pragma unroll 7
    for (int i = 0; i < SCAN_ITEMS; i++) {
        int idx = base + i;
        if (idx < n) {
            g_rowptr[idx] = run;
            g_fill[idx]   = run;
            run += g_cnt[idx];
        }
    }
    // thread 1023's chunk starts past n (1023*49=50127 > 50000), so its
    // excl == grand total; it writes the sentinel.
    if (tid == SCAN_THREADS - 1) g_rowptr[n] = run;
}

__global__ void scatter_kernel(const int* __restrict__ rows,
                               const int* __restrict__ cols, int nE) {
    int e = blockIdx.x * blockDim.x + threadIdx.x;
    if (e < nE) {
        int r = rows[e];
        int pos = atomicAdd(&g_fill[r], 1);
        g_adj[pos] = cols[e];
    }
}

// ============================================================
// Kernel 2: fused per-node attention. One warp per node.
// lane l owns dims [4l, 4l+4); head = l/8; 8-lane shfl reduce per head.
// out[n] = (sum_e exp(clip(q.k)) * v) / (sum_e exp + 1e-8)
// ============================================================
__global__ void attn_kernel(float* __restrict__ out, int N) {
    int warp = (blockIdx.x * blockDim.x + threadIdx.x) >> 5;
    int lane = threadIdx.x & 31;
    if (warp >= N) return;

    const float4 q = __ldg((const float4*)(g_Q + (size_t)warp * LATDIM) + lane);
    int beg = g_rowptr[warp];
    int end = g_rowptr[warp + 1];

    float ax = 0.f, ay = 0.f, az = 0.f, aw = 0.f, denom = 0.f;

    int c = (beg < end) ? g_adj[beg] : 0;
    for (int i = beg; i < end;) {
        const float4 k4 = __ldg((const float4*)(g_K + (size_t)c * LATDIM) + lane);
        const float4 v4 = __ldg((const float4*)(g_V + (size_t)c * LATDIM) + lane);
        i++;
        if (i < end) c = g_adj[i];   // prefetch next col index

        float p = q.x * k4.x + q.y * k4.y + q.z * k4.z + q.w * k4.w;
        p += __shfl_xor_sync(0xffffffffu, p, 1);
        p += __shfl_xor_sync(0xffffffffu, p, 2);
        p += __shfl_xor_sync(0xffffffffu, p, 4);
        p = fminf(fmaxf(p, -10.f), 10.f);
        float e = __expf(p);
        denom += e;
        ax = fmaf(e, v4.x, ax);
        ay = fmaf(e, v4.y, ay);
        az = fmaf(e, v4.z, az);
        aw = fmaf(e, v4.w, aw);
    }

    float inv = 1.f / (denom + 1e-8f);
    float4 o = make_float4(ax * inv, ay * inv, az * inv, aw * inv);
    *((float4*)out + (size_t)warp * 32 + lane) = o;
}

// ============================================================
extern "C" void kernel_launch(void* const* d_in, const int* in_sizes, int n_in,
                              void* d_out, int out_size) {
    const float* E    = (const float*)d_in[0];
    const float* qW   = (const float*)d_in[1];
    const float* kW   = (const float*)d_in[2];
    const float* vW   = (const float*)d_in[3];
    const int*   rows = (const int*)d_in[4];
    const int*   cols = (const int*)d_in[5];

    int N  = in_sizes[0] / LATDIM;
    int Eg = in_sizes[4];

    dim3 gg((N + 127) / 128, 3);
    gemm3_kernel<<<gg, 256>>>(E, qW, kW, vW, N);

    zero_kernel<<<(N + 255) / 256, 256>>>(N);
    hist_kernel<<<(Eg + 255) / 256, 256>>>(rows, Eg);
    scan_kernel<<<1, SCAN_THREADS>>>(N);
    scatter_kernel<<<(Eg + 255) / 256, 256>>>(rows, cols, Eg);

    attn_kernel<<<(N + 7) / 8, 256>>>((float*)d_out, N);
}

// round 3
// speedup vs baseline: 1.3305x; 1.3305x over previous
#include <cuda_runtime.h>
#include <cuda_bf16.h>

#define N_NODES 50000
#define N_EDGES 800000
#define LATDIM  128

typedef unsigned long long ull;

// ---- scratch (static device globals: the sanctioned no-alloc workaround) ----
__device__ float g_Q[N_NODES * LATDIM];
__device__ float g_K[N_NODES * LATDIM];
__device__ float g_V[N_NODES * LATDIM];
__device__ int   g_cnt[N_NODES];
__device__ int   g_excl[N_NODES];
__device__ int   g_bsum[64];
__device__ int   g_boff[64];      // g_boff[63] reserved for grand total
__device__ int   g_rowptr[N_NODES + 1];
__device__ int   g_fill[N_NODES];
__device__ int   g_adj[N_EDGES];

// ---- packed f32x2 helpers (FFMA2 path, sm_103a) ----
__device__ __forceinline__ ull pack2(float lo, float hi) {
    ull r;
    asm("mov.b64 %0, {%1, %2};" : "=l"(r)
        : "r"(__float_as_uint(lo)), "r"(__float_as_uint(hi)));
    return r;
}
__device__ __forceinline__ void fma2(ull& d, ull a, ull b) {
    asm("fma.rn.f32x2 %0, %1, %2, %3;" : "=l"(d) : "l"(a), "l"(b), "l"(d));
}
__device__ __forceinline__ void unpack2(ull v, float& lo, float& hi) {
    unsigned ulo, uhi;
    asm("mov.b64 {%0, %1}, %2;" : "=r"(ulo), "=r"(uhi) : "l"(v));
    lo = __uint_as_float(ulo);
    hi = __uint_as_float(uhi);
}

// ============================================================
// Kernel 1: fused Q/K/V projection. grid = (ceil(N/128), 3).
// Block 256 threads, each computes 8 rows x 8 cols using f32x2 FMAs.
// ============================================================
__global__ __launch_bounds__(256, 2)
void gemm3_kernel(const float* __restrict__ E,
                  const float* __restrict__ qW,
                  const float* __restrict__ kW,
                  const float* __restrict__ vW,
                  int N)
{
    __shared__ float As[32][132];   // A tile transposed: As[k][row]
    __shared__ float Bs[32][128];   // W tile: Bs[k][col]

    const float* W   = (blockIdx.y == 0) ? qW : (blockIdx.y == 1 ? kW : vW);
    float*       Out = (blockIdx.y == 0) ? g_Q : (blockIdx.y == 1 ? g_K : g_V);

    const int row0 = blockIdx.x * 128;
    const int tid  = threadIdx.x;
    const int tr   = (tid >> 4) << 3;   // thread row base (0..120)
    const int tc   = (tid & 15) << 3;   // thread col base (0..120)

    ull acc[8][4];
#pragma unroll
    for (int i = 0; i < 8; i++)
#pragma unroll
        for (int j = 0; j < 4; j++) acc[i][j] = 0ULL;

    for (int kc = 0; kc < LATDIM; kc += 32) {
        // load W chunk (32 x 128) into Bs
#pragma unroll
        for (int v = tid; v < 32 * 32; v += 256) {
            int k = v >> 5, c4 = v & 31;
            *(float4*)&Bs[k][c4 * 4] =
                __ldg((const float4*)(W + (size_t)(kc + k) * LATDIM) + c4);
        }
        // load A chunk (128 rows x 32 k) transposed into As
        {
            int kq = (tid & 7) * 4;
            int rb = tid >> 3;
#pragma unroll
            for (int rr = 0; rr < 4; rr++) {
                int r = rb + rr * 32;
                int grow = row0 + r;
                float4 a = (grow < N)
                    ? __ldg((const float4*)(E + (size_t)grow * LATDIM + kc + kq))
                    : make_float4(0.f, 0.f, 0.f, 0.f);
                As[kq + 0][r] = a.x;
                As[kq + 1][r] = a.y;
                As[kq + 2][r] = a.z;
                As[kq + 3][r] = a.w;
            }
        }
        __syncthreads();

#pragma unroll 8
        for (int k = 0; k < 32; k++) {
            float4 a0 = *(const float4*)&As[k][tr];
            float4 a1 = *(const float4*)&As[k][tr + 4];
            ulonglong2 bq0 = *(const ulonglong2*)&Bs[k][tc];
            ulonglong2 bq1 = *(const ulonglong2*)&Bs[k][tc + 4];
            ull bb[4] = {bq0.x, bq0.y, bq1.x, bq1.y};
            ull aa[8];
            aa[0] = pack2(a0.x, a0.x); aa[1] = pack2(a0.y, a0.y);
            aa[2] = pack2(a0.z, a0.z); aa[3] = pack2(a0.w, a0.w);
            aa[4] = pack2(a1.x, a1.x); aa[5] = pack2(a1.y, a1.y);
            aa[6] = pack2(a1.z, a1.z); aa[7] = pack2(a1.w, a1.w);
#pragma unroll
            for (int i = 0; i < 8; i++) {
                fma2(acc[i][0], aa[i], bb[0]);
                fma2(acc[i][1], aa[i], bb[1]);
                fma2(acc[i][2], aa[i], bb[2]);
                fma2(acc[i][3], aa[i], bb[3]);
            }
        }
        __syncthreads();
    }

#pragma unroll
    for (int i = 0; i < 8; i++) {
        int grow = row0 + tr + i;
        if (grow < N) {
            float o[8];
#pragma unroll
            for (int j = 0; j < 4; j++) unpack2(acc[i][j], o[2 * j], o[2 * j + 1]);
            *(float4*)(Out + (size_t)grow * LATDIM + tc)     = make_float4(o[0], o[1], o[2], o[3]);
            *(float4*)(Out + (size_t)grow * LATDIM + tc + 4) = make_float4(o[4], o[5], o[6], o[7]);
        }
    }
}

// ============================================================
// CSR build: zero -> histogram -> 3-pass coalesced scan -> scatter
// ============================================================
__global__ void zero_kernel(int n) {
    int i = blockIdx.x * blockDim.x + threadIdx.x;
    if (i < n) g_cnt[i] = 0;
}

__global__ void hist_kernel(const int* __restrict__ rows, int nE) {
    int e = blockIdx.x * blockDim.x + threadIdx.x;
    if (e < nE) atomicAdd(&g_cnt[rows[e]], 1);
}

// pass 1: per-block coalesced inclusive scan; write per-elem exclusive + block sum
__global__ __launch_bounds__(1024)
void scan_pass1(int n) {
    __shared__ int warp_sums[32];
    const int tid  = threadIdx.x;
    const int lane = tid & 31;
    const int wid  = tid >> 5;
    const int i    = blockIdx.x * 1024 + tid;

    int v = (i < n) ? g_cnt[i] : 0;

    // inclusive warp scan
    int s = v;
#pragma unroll
    for (int o = 1; o < 32; o <<= 1) {
        int t = __shfl_up_sync(0xffffffffu, s, o);
        if (lane >= o) s += t;
    }
    if (lane == 31) warp_sums[wid] = s;
    __syncthreads();

    if (wid == 0) {
        int w = warp_sums[lane];
#pragma unroll
        for (int o = 1; o < 32; o <<= 1) {
            int t = __shfl_up_sync(0xffffffffu, w, o);
            if (lane >= o) w += t;
        }
        warp_sums[lane] = w;
    }
    __syncthreads();

    int incl = s + (wid > 0 ? warp_sums[wid - 1] : 0);
    if (i < n) g_excl[i] = incl - v;
    if (tid == 1023) g_bsum[blockIdx.x] = incl;
}

// pass 2: one warp scans the (<=63) block sums -> exclusive offsets + total
__global__ void scan_pass2(int nb) {
    int lane = threadIdx.x;                 // 32 threads
    int a0 = (lane < nb)      ? g_bsum[lane]      : 0;
    int b0 = (lane + 32 < nb) ? g_bsum[lane + 32] : 0;
    int a = a0, b = b0;
#pragma unroll
    for (int o = 1; o < 32; o <<= 1) {
        int t = __shfl_up_sync(0xffffffffu, a, o);
        if (lane >= o) a += t;
    }
    int lowTot = __shfl_sync(0xffffffffu, a, 31);
#pragma unroll
    for (int o = 1; o < 32; o <<= 1) {
        int t = __shfl_up_sync(0xffffffffu, b, o);
        if (lane >= o) b += t;
    }
    b += lowTot;
    g_boff[lane] = a - a0;                  // exclusive offset for block `lane`
    if (lane + 32 < 63) g_boff[lane + 32] = b - b0;
    if (lane == 31) g_boff[63] = __shfl_sync(0xffffffffu, b, 31);  // grand total
}

// pass 3: add block offsets, materialize rowptr/fill + sentinel
__global__ __launch_bounds__(1024)
void scan_pass3(int n) {
    int i = blockIdx.x * 1024 + threadIdx.x;
    if (i < n) {
        int r = g_excl[i] + g_boff[i >> 10];
        g_rowptr[i] = r;
        g_fill[i]   = r;
    } else if (i == n) {
        g_rowptr[n] = g_boff[63];
    }
}

__global__ void scatter_kernel(const int* __restrict__ rows,
                               const int* __restrict__ cols, int nE) {
    int e = blockIdx.x * blockDim.x + threadIdx.x;
    if (e < nE) {
        int r = rows[e];
        int pos = atomicAdd(&g_fill[r], 1);
        g_adj[pos] = cols[e];
    }
}

// ============================================================
// Kernel 2: fused per-node attention. One warp per node.
// lane l owns dims [4l, 4l+4); head = l/8; 8-lane shfl reduce per head.
// out[n] = (sum_e exp(clip(q.k)) * v) / (sum_e exp + 1e-8)
// ============================================================
__global__ void attn_kernel(float* __restrict__ out, int N) {
    int warp = (blockIdx.x * blockDim.x + threadIdx.x) >> 5;
    int lane = threadIdx.x & 31;
    if (warp >= N) return;

    const float4 q = __ldg((const float4*)(g_Q + (size_t)warp * LATDIM) + lane);
    int beg = g_rowptr[warp];
    int end = g_rowptr[warp + 1];

    float ax = 0.f, ay = 0.f, az = 0.f, aw = 0.f, denom = 0.f;

    int c = (beg < end) ? g_adj[beg] : 0;
    for (int i = beg; i < end;) {
        const float4 k4 = __ldg((const float4*)(g_K + (size_t)c * LATDIM) + lane);
        const float4 v4 = __ldg((const float4*)(g_V + (size_t)c * LATDIM) + lane);
        i++;
        if (i < end) c = g_adj[i];   // prefetch next col index

        float p = q.x * k4.x + q.y * k4.y + q.z * k4.z + q.w * k4.w;
        p += __shfl_xor_sync(0xffffffffu, p, 1);
        p += __shfl_xor_sync(0xffffffffu, p, 2);
        p += __shfl_xor_sync(0xffffffffu, p, 4);
        p = fminf(fmaxf(p, -10.f), 10.f);
        float e = __expf(p);
        denom += e;
        ax = fmaf(e, v4.x, ax);
        ay = fmaf(e, v4.y, ay);
        az = fmaf(e, v4.z, az);
        aw = fmaf(e, v4.w, aw);
    }

    float inv = 1.f / (denom + 1e-8f);
    float4 o = make_float4(ax * inv, ay * inv, az * inv, aw * inv);
    *((float4*)out + (size_t)warp * 32 + lane) = o;
}

// ============================================================
extern "C" void kernel_launch(void* const* d_in, const int* in_sizes, int n_in,
                              void* d_out, int out_size) {
    const float* E    = (const float*)d_in[0];
    const float* qW   = (const float*)d_in[1];
    const float* kW   = (const float*)d_in[2];
    const float* vW   = (const float*)d_in[3];
    const int*   rows = (const int*)d_in[4];
    const int*   cols = (const int*)d_in[5];

    int N  = in_sizes[0] / LATDIM;
    int Eg = in_sizes[4];

    dim3 gg((N + 127) / 128, 3);
    gemm3_kernel<<<gg, 256>>>(E, qW, kW, vW, N);

    int nb = (N + 1023) / 1024;
    zero_kernel<<<(N + 255) / 256, 256>>>(N);
    hist_kernel<<<(Eg + 255) / 256, 256>>>(rows, Eg);
    scan_pass1<<<nb, 1024>>>(N);
    scan_pass2<<<1, 32>>>(nb);
    scan_pass3<<<(N + 1024) / 1024, 1024>>>(N);   // covers i == N sentinel
    scatter_kernel<<<(Eg + 255) / 256, 256>>>(rows, cols, Eg);

    attn_kernel<<<(N + 7) / 8, 256>>>((float*)d_out, N);
}

// round 4
// speedup vs baseline: 1.3812x; 1.0381x over previous
#include <cuda_runtime.h>
#include <cuda_bf16.h>

#define N_NODES 50000
#define N_EDGES 800000
#define LATDIM  128

typedef unsigned long long ull;

// ---- scratch (static device globals: the sanctioned no-alloc workaround) ----
__device__ float g_Q[N_NODES * LATDIM];
__device__ float g_K[N_NODES * LATDIM];
__device__ float g_V[N_NODES * LATDIM];
__device__ int   g_cnt[N_NODES];
__device__ int   g_excl[N_NODES];
__device__ int   g_bsum[64];
__device__ int   g_boff[64];      // g_boff[63] reserved for grand total
__device__ int   g_rowptr[N_NODES + 1];
__device__ int   g_fill[N_NODES];
__device__ int   g_adj[N_EDGES];

// ---- packed f32x2 helpers (FFMA2 path, sm_103a) ----
__device__ __forceinline__ ull pack2(float lo, float hi) {
    ull r;
    asm("mov.b64 %0, {%1, %2};" : "=l"(r)
        : "r"(__float_as_uint(lo)), "r"(__float_as_uint(hi)));
    return r;
}
__device__ __forceinline__ void fma2(ull& d, ull a, ull b) {
    asm("fma.rn.f32x2 %0, %1, %2, %3;" : "=l"(d) : "l"(a), "l"(b), "l"(d));
}
__device__ __forceinline__ void unpack2(ull v, float& lo, float& hi) {
    unsigned ulo, uhi;
    asm("mov.b64 {%0, %1}, %2;" : "=r"(ulo), "=r"(uhi) : "l"(v));
    lo = __uint_as_float(ulo);
    hi = __uint_as_float(uhi);
}

// ============================================================
// Kernel 1: fused Q/K/V projection. grid = (ceil(N/128), 3).
// Block 256 threads, each computes 8 rows x 8 cols using f32x2 FMAs.
// ============================================================
__global__ __launch_bounds__(256, 2)
void gemm3_kernel(const float* __restrict__ E,
                  const float* __restrict__ qW,
                  const float* __restrict__ kW,
                  const float* __restrict__ vW,
                  int N)
{
    __shared__ float As[32][132];   // A tile transposed: As[k][row]
    __shared__ float Bs[32][128];   // W tile: Bs[k][col]

    const float* W   = (blockIdx.y == 0) ? qW : (blockIdx.y == 1 ? kW : vW);
    float*       Out = (blockIdx.y == 0) ? g_Q : (blockIdx.y == 1 ? g_K : g_V);

    const int row0 = blockIdx.x * 128;
    const int tid  = threadIdx.x;
    const int tr   = (tid >> 4) << 3;   // thread row base (0..120)
    const int tc   = (tid & 15) << 3;   // thread col base (0..120)

    ull acc[8][4];
#pragma unroll
    for (int i = 0; i < 8; i++)
#pragma unroll
        for (int j = 0; j < 4; j++) acc[i][j] = 0ULL;

    for (int kc = 0; kc < LATDIM; kc += 32) {
        // load W chunk (32 x 128) into Bs
#pragma unroll
        for (int v = tid; v < 32 * 32; v += 256) {
            int k = v >> 5, c4 = v & 31;
            *(float4*)&Bs[k][c4 * 4] =
                __ldg((const float4*)(W + (size_t)(kc + k) * LATDIM) + c4);
        }
        // load A chunk (128 rows x 32 k) transposed into As
        {
            int kq = (tid & 7) * 4;
            int rb = tid >> 3;
#pragma unroll
            for (int rr = 0; rr < 4; rr++) {
                int r = rb + rr * 32;
                int grow = row0 + r;
                float4 a = (grow < N)
                    ? __ldg((const float4*)(E + (size_t)grow * LATDIM + kc + kq))
                    : make_float4(0.f, 0.f, 0.f, 0.f);
                As[kq + 0][r] = a.x;
                As[kq + 1][r] = a.y;
                As[kq + 2][r] = a.z;
                As[kq + 3][r] = a.w;
            }
        }
        __syncthreads();

#pragma unroll 8
        for (int k = 0; k < 32; k++) {
            float4 a0 = *(const float4*)&As[k][tr];
            float4 a1 = *(const float4*)&As[k][tr + 4];
            ulonglong2 bq0 = *(const ulonglong2*)&Bs[k][tc];
            ulonglong2 bq1 = *(const ulonglong2*)&Bs[k][tc + 4];
            ull bb[4] = {bq0.x, bq0.y, bq1.x, bq1.y};
            ull aa[8];
            aa[0] = pack2(a0.x, a0.x); aa[1] = pack2(a0.y, a0.y);
            aa[2] = pack2(a0.z, a0.z); aa[3] = pack2(a0.w, a0.w);
            aa[4] = pack2(a1.x, a1.x); aa[5] = pack2(a1.y, a1.y);
            aa[6] = pack2(a1.z, a1.z); aa[7] = pack2(a1.w, a1.w);
#pragma unroll
            for (int i = 0; i < 8; i++) {
                fma2(acc[i][0], aa[i], bb[0]);
                fma2(acc[i][1], aa[i], bb[1]);
                fma2(acc[i][2], aa[i], bb[2]);
                fma2(acc[i][3], aa[i], bb[3]);
            }
        }
        __syncthreads();
    }

#pragma unroll
    for (int i = 0; i < 8; i++) {
        int grow = row0 + tr + i;
        if (grow < N) {
            float o[8];
#pragma unroll
            for (int j = 0; j < 4; j++) unpack2(acc[i][j], o[2 * j], o[2 * j + 1]);
            *(float4*)(Out + (size_t)grow * LATDIM + tc)     = make_float4(o[0], o[1], o[2], o[3]);
            *(float4*)(Out + (size_t)grow * LATDIM + tc + 4) = make_float4(o[4], o[5], o[6], o[7]);
        }
    }
}

// ============================================================
// CSR build: zero -> histogram -> 3-pass coalesced scan -> scatter
// ============================================================
__global__ void zero_kernel(int n) {
    int i = blockIdx.x * blockDim.x + threadIdx.x;
    if (i < n) g_cnt[i] = 0;
}

__global__ void hist_kernel(const int* __restrict__ rows, int nE) {
    int e = blockIdx.x * blockDim.x + threadIdx.x;
    if (e < nE) atomicAdd(&g_cnt[rows[e]], 1);
}

// pass 1: per-block coalesced inclusive scan; write per-elem exclusive + block sum
__global__ __launch_bounds__(1024)
void scan_pass1(int n) {
    __shared__ int warp_sums[32];
    const int tid  = threadIdx.x;
    const int lane = tid & 31;
    const int wid  = tid >> 5;
    const int i    = blockIdx.x * 1024 + tid;

    int v = (i < n) ? g_cnt[i] : 0;

    // inclusive warp scan
    int s = v;
#pragma unroll
    for (int o = 1; o < 32; o <<= 1) {
        int t = __shfl_up_sync(0xffffffffu, s, o);
        if (lane >= o) s += t;
    }
    if (lane == 31) warp_sums[wid] = s;
    __syncthreads();

    if (wid == 0) {
        int w = warp_sums[lane];
#pragma unroll
        for (int o = 1; o < 32; o <<= 1) {
            int t = __shfl_up_sync(0xffffffffu, w, o);
            if (lane >= o) w += t;
        }
        warp_sums[lane] = w;
    }
    __syncthreads();

    int incl = s + (wid > 0 ? warp_sums[wid - 1] : 0);
    if (i < n) g_excl[i] = incl - v;
    if (tid == 1023) g_bsum[blockIdx.x] = incl;
}

// pass 2: one warp scans the (<=63) block sums -> exclusive offsets + total
__global__ void scan_pass2(int nb) {
    int lane = threadIdx.x;                 // 32 threads
    int a0 = (lane < nb)      ? g_bsum[lane]      : 0;
    int b0 = (lane + 32 < nb) ? g_bsum[lane + 32] : 0;
    int a = a0, b = b0;
#pragma unroll
    for (int o = 1; o < 32; o <<= 1) {
        int t = __shfl_up_sync(0xffffffffu, a, o);
        if (lane >= o) a += t;
    }
    int lowTot = __shfl_sync(0xffffffffu, a, 31);
#pragma unroll
    for (int o = 1; o < 32; o <<= 1) {
        int t = __shfl_up_sync(0xffffffffu, b, o);
        if (lane >= o) b += t;
    }
    b += lowTot;
    g_boff[lane] = a - a0;                  // exclusive offset for block `lane`
    if (lane + 32 < 63) g_boff[lane + 32] = b - b0;
    if (lane == 31) g_boff[63] = __shfl_sync(0xffffffffu, b, 31);  // grand total
}

// pass 3: add block offsets, materialize rowptr/fill + sentinel
__global__ __launch_bounds__(1024)
void scan_pass3(int n) {
    int i = blockIdx.x * 1024 + threadIdx.x;
    if (i < n) {
        int r = g_excl[i] + g_boff[i >> 10];
        g_rowptr[i] = r;
        g_fill[i]   = r;
    } else if (i == n) {
        g_rowptr[n] = g_boff[63];
    }
}

__global__ void scatter_kernel(const int* __restrict__ rows,
                               const int* __restrict__ cols, int nE) {
    int e = blockIdx.x * blockDim.x + threadIdx.x;
    if (e < nE) {
        int r = rows[e];
        int pos = atomicAdd(&g_fill[r], 1);
        g_adj[pos] = cols[e];
    }
}

// ============================================================
// Kernel 2: fused per-node attention. One warp per node.
// lane l owns dims [4l, 4l+4); head = l/8; 8-lane shfl reduce per head.
// 2-edge unroll: 4 independent LDG.128 in flight per iteration.
// out[n] = (sum_e exp(clip(q.k)) * v) / (sum_e exp + 1e-8)
// ============================================================
__global__ void attn_kernel(float* __restrict__ out, int N) {
    int warp = (blockIdx.x * blockDim.x + threadIdx.x) >> 5;
    int lane = threadIdx.x & 31;
    if (warp >= N) return;

    const float4 q = __ldg((const float4*)(g_Q + (size_t)warp * LATDIM) + lane);
    int beg = g_rowptr[warp];
    int end = g_rowptr[warp + 1];

    float ax = 0.f, ay = 0.f, az = 0.f, aw = 0.f, denom = 0.f;

    int i = beg;
    for (; i + 2 <= end; i += 2) {
        int c0 = __ldg(g_adj + i);
        int c1 = __ldg(g_adj + i + 1);
        const float4 k0 = __ldg((const float4*)(g_K + (size_t)c0 * LATDIM) + lane);
        const float4 v0 = __ldg((const float4*)(g_V + (size_t)c0 * LATDIM) + lane);
        const float4 k1 = __ldg((const float4*)(g_K + (size_t)c1 * LATDIM) + lane);
        const float4 v1 = __ldg((const float4*)(g_V + (size_t)c1 * LATDIM) + lane);

        float p0 = q.x * k0.x + q.y * k0.y + q.z * k0.z + q.w * k0.w;
        float p1 = q.x * k1.x + q.y * k1.y + q.z * k1.z + q.w * k1.w;
        p0 += __shfl_xor_sync(0xffffffffu, p0, 1);
        p1 += __shfl_xor_sync(0xffffffffu, p1, 1);
        p0 += __shfl_xor_sync(0xffffffffu, p0, 2);
        p1 += __shfl_xor_sync(0xffffffffu, p1, 2);
        p0 += __shfl_xor_sync(0xffffffffu, p0, 4);
        p1 += __shfl_xor_sync(0xffffffffu, p1, 4);
        p0 = fminf(fmaxf(p0, -10.f), 10.f);
        p1 = fminf(fmaxf(p1, -10.f), 10.f);
        float e0 = __expf(p0);
        float e1 = __expf(p1);
        denom += e0 + e1;
        ax = fmaf(e0, v0.x, ax); ax = fmaf(e1, v1.x, ax);
        ay = fmaf(e0, v0.y, ay); ay = fmaf(e1, v1.y, ay);
        az = fmaf(e0, v0.z, az); az = fmaf(e1, v1.z, az);
        aw = fmaf(e0, v0.w, aw); aw = fmaf(e1, v1.w, aw);
    }
    if (i < end) {
        int c = __ldg(g_adj + i);
        const float4 k4 = __ldg((const float4*)(g_K + (size_t)c * LATDIM) + lane);
        const float4 v4 = __ldg((const float4*)(g_V + (size_t)c * LATDIM) + lane);
        float p = q.x * k4.x + q.y * k4.y + q.z * k4.z + q.w * k4.w;
        p += __shfl_xor_sync(0xffffffffu, p, 1);
        p += __shfl_xor_sync(0xffffffffu, p, 2);
        p += __shfl_xor_sync(0xffffffffu, p, 4);
        p = fminf(fmaxf(p, -10.f), 10.f);
        float e = __expf(p);
        denom += e;
        ax = fmaf(e, v4.x, ax);
        ay = fmaf(e, v4.y, ay);
        az = fmaf(e, v4.z, az);
        aw = fmaf(e, v4.w, aw);
    }

    float inv = 1.f / (denom + 1e-8f);
    float4 o = make_float4(ax * inv, ay * inv, az * inv, aw * inv);
    *((float4*)out + (size_t)warp * 32 + lane) = o;
}

// ============================================================
extern "C" void kernel_launch(void* const* d_in, const int* in_sizes, int n_in,
                              void* d_out, int out_size) {
    const float* E    = (const float*)d_in[0];
    const float* qW   = (const float*)d_in[1];
    const float* kW   = (const float*)d_in[2];
    const float* vW   = (const float*)d_in[3];
    const int*   rows = (const int*)d_in[4];
    const int*   cols = (const int*)d_in[5];

    int N  = in_sizes[0] / LATDIM;
    int Eg = in_sizes[4];

    int nb = (N + 1023) / 1024;

    // CSR front-half first; gemm3 placed 4th so the ncu capture slot
    // (empirically the 4th launch) profiles the GEMM this round.
    zero_kernel<<<(N + 255) / 256, 256>>>(N);
    hist_kernel<<<(Eg + 255) / 256, 256>>>(rows, Eg);
    scan_pass1<<<nb, 1024>>>(N);

    dim3 gg((N + 127) / 128, 3);
    gemm3_kernel<<<gg, 256>>>(E, qW, kW, vW, N);

    scan_pass2<<<1, 32>>>(nb);
    scan_pass3<<<(N + 1024) / 1024, 1024>>>(N);   // covers i == N sentinel
    scatter_kernel<<<(Eg + 255) / 256, 256>>>(rows, cols, Eg);

    attn_kernel<<<(N + 7) / 8, 256>>>((float*)d_out, N);
}

// round 5
// speedup vs baseline: 1.4891x; 1.0781x over previous
#include <cuda_runtime.h>
#include <cuda_bf16.h>

#define N_NODES 50000
#define N_EDGES 800000
#define LATDIM  128

typedef unsigned long long ull;

// ---- scratch (static device globals: the sanctioned no-alloc workaround) ----
__device__ float g_Q[N_NODES * LATDIM];
__device__ float g_K[N_NODES * LATDIM];
__device__ float g_V[N_NODES * LATDIM];
__device__ int   g_cnt[N_NODES];
__device__ int   g_excl[N_NODES];
__device__ int   g_bsum[64];
__device__ int   g_boff[64];      // g_boff[63] reserved for grand total
__device__ int   g_rowptr[N_NODES + 1];
__device__ int   g_fill[N_NODES];
__device__ int   g_adj[N_EDGES];

// ---- packed f32x2 helpers (FFMA2 path, sm_103a) ----
__device__ __forceinline__ ull pack2(float lo, float hi) {
    ull r;
    asm("mov.b64 %0, {%1, %2};" : "=l"(r)
        : "r"(__float_as_uint(lo)), "r"(__float_as_uint(hi)));
    return r;
}
__device__ __forceinline__ void fma2(ull& d, ull a, ull b) {
    asm("fma.rn.f32x2 %0, %1, %2, %3;" : "=l"(d) : "l"(a), "l"(b), "l"(d));
}
__device__ __forceinline__ void unpack2(ull v, float& lo, float& hi) {
    unsigned ulo, uhi;
    asm("mov.b64 {%0, %1}, %2;" : "=r"(ulo), "=r"(uhi) : "l"(v));
    lo = __uint_as_float(ulo);
    hi = __uint_as_float(uhi);
}

// ============================================================
// Kernel 1: fused Q/K/V projection. grid = (ceil(N/128), 3).
// Block 256 threads, each computes 8 rows x (4+4) cols using f32x2 FMAs.
// Col blocks are 64 apart so warp LDS of B is a contiguous 256B span
// (conflict-free) instead of the old 32B-stride 4-way-conflicted pattern.
// ============================================================
__global__ __launch_bounds__(256, 2)
void gemm3_kernel(const float* __restrict__ E,
                  const float* __restrict__ qW,
                  const float* __restrict__ kW,
                  const float* __restrict__ vW,
                  int N)
{
    __shared__ float As[32][132];   // A tile transposed: As[k][row]
    __shared__ float Bs[32][128];   // W tile: Bs[k][col]

    const float* W   = (blockIdx.y == 0) ? qW : (blockIdx.y == 1 ? kW : vW);
    float*       Out = (blockIdx.y == 0) ? g_Q : (blockIdx.y == 1 ? g_K : g_V);

    const int row0 = blockIdx.x * 128;
    const int tid  = threadIdx.x;
    const int tr   = (tid >> 4) << 3;   // thread row base (0..120)
    const int tc   = (tid & 15) << 2;   // col block 0: cols [tc, tc+4)
                                        // col block 1: cols [tc+64, tc+68)

    ull acc[8][4];
#pragma unroll
    for (int i = 0; i < 8; i++)
#pragma unroll
        for (int j = 0; j < 4; j++) acc[i][j] = 0ULL;

    for (int kc = 0; kc < LATDIM; kc += 32) {
        // load W chunk (32 x 128) into Bs
#pragma unroll
        for (int v = tid; v < 32 * 32; v += 256) {
            int k = v >> 5, c4 = v & 31;
            *(float4*)&Bs[k][c4 * 4] =
                __ldg((const float4*)(W + (size_t)(kc + k) * LATDIM) + c4);
        }
        // load A chunk (128 rows x 32 k) transposed into As
        {
            int kq = (tid & 7) * 4;
            int rb = tid >> 3;
#pragma unroll
            for (int rr = 0; rr < 4; rr++) {
                int r = rb + rr * 32;
                int grow = row0 + r;
                float4 a = (grow < N)
                    ? __ldg((const float4*)(E + (size_t)grow * LATDIM + kc + kq))
                    : make_float4(0.f, 0.f, 0.f, 0.f);
                As[kq + 0][r] = a.x;
                As[kq + 1][r] = a.y;
                As[kq + 2][r] = a.z;
                As[kq + 3][r] = a.w;
            }
        }
        __syncthreads();

#pragma unroll 8
        for (int k = 0; k < 32; k++) {
            float4 a0 = *(const float4*)&As[k][tr];        // broadcast
            float4 a1 = *(const float4*)&As[k][tr + 4];    // broadcast
            ulonglong2 bq0 = *(const ulonglong2*)&Bs[k][tc];       // contiguous
            ulonglong2 bq1 = *(const ulonglong2*)&Bs[k][tc + 64];  // contiguous
            ull bb[4] = {bq0.x, bq0.y, bq1.x, bq1.y};
            ull aa[8];
            aa[0] = pack2(a0.x, a0.x); aa[1] = pack2(a0.y, a0.y);
            aa[2] = pack2(a0.z, a0.z); aa[3] = pack2(a0.w, a0.w);
            aa[4] = pack2(a1.x, a1.x); aa[5] = pack2(a1.y, a1.y);
            aa[6] = pack2(a1.z, a1.z); aa[7] = pack2(a1.w, a1.w);
#pragma unroll
            for (int i = 0; i < 8; i++) {
                fma2(acc[i][0], aa[i], bb[0]);
                fma2(acc[i][1], aa[i], bb[1]);
                fma2(acc[i][2], aa[i], bb[2]);
                fma2(acc[i][3], aa[i], bb[3]);
            }
        }
        __syncthreads();
    }

#pragma unroll
    for (int i = 0; i < 8; i++) {
        int grow = row0 + tr + i;
        if (grow < N) {
            float o[8];
#pragma unroll
            for (int j = 0; j < 4; j++) unpack2(acc[i][j], o[2 * j], o[2 * j + 1]);
            *(float4*)(Out + (size_t)grow * LATDIM + tc)      = make_float4(o[0], o[1], o[2], o[3]);
            *(float4*)(Out + (size_t)grow * LATDIM + tc + 64) = make_float4(o[4], o[5], o[6], o[7]);
        }
    }
}

// ============================================================
// CSR build: zero -> histogram -> 3-pass coalesced scan -> scatter
// ============================================================
__global__ void zero_kernel(int n) {
    int i = blockIdx.x * blockDim.x + threadIdx.x;
    if (i < n) g_cnt[i] = 0;
}

__global__ void hist_kernel(const int* __restrict__ rows, int nE) {
    int e = blockIdx.x * blockDim.x + threadIdx.x;
    if (e < nE) atomicAdd(&g_cnt[rows[e]], 1);
}

// pass 1: per-block coalesced inclusive scan; write per-elem exclusive + block sum
__global__ __launch_bounds__(1024)
void scan_pass1(int n) {
    __shared__ int warp_sums[32];
    const int tid  = threadIdx.x;
    const int lane = tid & 31;
    const int wid  = tid >> 5;
    const int i    = blockIdx.x * 1024 + tid;

    int v = (i < n) ? g_cnt[i] : 0;

    // inclusive warp scan
    int s = v;
#pragma unroll
    for (int o = 1; o < 32; o <<= 1) {
        int t = __shfl_up_sync(0xffffffffu, s, o);
        if (lane >= o) s += t;
    }
    if (lane == 31) warp_sums[wid] = s;
    __syncthreads();

    if (wid == 0) {
        int w = warp_sums[lane];
#pragma unroll
        for (int o = 1; o < 32; o <<= 1) {
            int t = __shfl_up_sync(0xffffffffu, w, o);
            if (lane >= o) w += t;
        }
        warp_sums[lane] = w;
    }
    __syncthreads();

    int incl = s + (wid > 0 ? warp_sums[wid - 1] : 0);
    if (i < n) g_excl[i] = incl - v;
    if (tid == 1023) g_bsum[blockIdx.x] = incl;
}

// pass 2: one warp scans the (<=63) block sums -> exclusive offsets + total
__global__ void scan_pass2(int nb) {
    int lane = threadIdx.x;                 // 32 threads
    int a0 = (lane < nb)      ? g_bsum[lane]      : 0;
    int b0 = (lane + 32 < nb) ? g_bsum[lane + 32] : 0;
    int a = a0, b = b0;
#pragma unroll
    for (int o = 1; o < 32; o <<= 1) {
        int t = __shfl_up_sync(0xffffffffu, a, o);
        if (lane >= o) a += t;
    }
    int lowTot = __shfl_sync(0xffffffffu, a, 31);
#pragma unroll
    for (int o = 1; o < 32; o <<= 1) {
        int t = __shfl_up_sync(0xffffffffu, b, o);
        if (lane >= o) b += t;
    }
    b += lowTot;
    g_boff[lane] = a - a0;                  // exclusive offset for block `lane`
    if (lane + 32 < 63) g_boff[lane + 32] = b - b0;
    if (lane == 31) g_boff[63] = __shfl_sync(0xffffffffu, b, 31);  // grand total
}

// pass 3: add block offsets, materialize rowptr/fill + sentinel
__global__ __launch_bounds__(1024)
void scan_pass3(int n) {
    int i = blockIdx.x * 1024 + threadIdx.x;
    if (i < n) {
        int r = g_excl[i] + g_boff[i >> 10];
        g_rowptr[i] = r;
        g_fill[i]   = r;
    } else if (i == n) {
        g_rowptr[n] = g_boff[63];
    }
}

__global__ void scatter_kernel(const int* __restrict__ rows,
                               const int* __restrict__ cols, int nE) {
    int e = blockIdx.x * blockDim.x + threadIdx.x;
    if (e < nE) {
        int r = rows[e];
        int pos = atomicAdd(&g_fill[r], 1);
        g_adj[pos] = cols[e];
    }
}

// ============================================================
// Kernel 2: fused per-node attention. One warp per node.
// lane l owns dims [4l, 4l+4); head = l/8; 8-lane shfl reduce per head.
// 2-edge unroll: 4 independent LDG.128 in flight per iteration.
// out[n] = (sum_e exp(clip(q.k)) * v) / (sum_e exp + 1e-8)
// ============================================================
__global__ void attn_kernel(float* __restrict__ out, int N) {
    int warp = (blockIdx.x * blockDim.x + threadIdx.x) >> 5;
    int lane = threadIdx.x & 31;
    if (warp >= N) return;

    const float4 q = __ldg((const float4*)(g_Q + (size_t)warp * LATDIM) + lane);
    int beg = g_rowptr[warp];
    int end = g_rowptr[warp + 1];

    float ax = 0.f, ay = 0.f, az = 0.f, aw = 0.f, denom = 0.f;

    int i = beg;
    for (; i + 2 <= end; i += 2) {
        int c0 = __ldg(g_adj + i);
        int c1 = __ldg(g_adj + i + 1);
        const float4 k0 = __ldg((const float4*)(g_K + (size_t)c0 * LATDIM) + lane);
        const float4 v0 = __ldg((const float4*)(g_V + (size_t)c0 * LATDIM) + lane);
        const float4 k1 = __ldg((const float4*)(g_K + (size_t)c1 * LATDIM) + lane);
        const float4 v1 = __ldg((const float4*)(g_V + (size_t)c1 * LATDIM) + lane);

        float p0 = q.x * k0.x + q.y * k0.y + q.z * k0.z + q.w * k0.w;
        float p1 = q.x * k1.x + q.y * k1.y + q.z * k1.z + q.w * k1.w;
        p0 += __shfl_xor_sync(0xffffffffu, p0, 1);
        p1 += __shfl_xor_sync(0xffffffffu, p1, 1);
        p0 += __shfl_xor_sync(0xffffffffu, p0, 2);
        p1 += __shfl_xor_sync(0xffffffffu, p1, 2);
        p0 += __shfl_xor_sync(0xffffffffu, p0, 4);
        p1 += __shfl_xor_sync(0xffffffffu, p1, 4);
        p0 = fminf(fmaxf(p0, -10.f), 10.f);
        p1 = fminf(fmaxf(p1, -10.f), 10.f);
        float e0 = __expf(p0);
        float e1 = __expf(p1);
        denom += e0 + e1;
        ax = fmaf(e0, v0.x, ax); ax = fmaf(e1, v1.x, ax);
        ay = fmaf(e0, v0.y, ay); ay = fmaf(e1, v1.y, ay);
        az = fmaf(e0, v0.z, az); az = fmaf(e1, v1.z, az);
        aw = fmaf(e0, v0.w, aw); aw = fmaf(e1, v1.w, aw);
    }
    if (i < end) {
        int c = __ldg(g_adj + i);
        const float4 k4 = __ldg((const float4*)(g_K + (size_t)c * LATDIM) + lane);
        const float4 v4 = __ldg((const float4*)(g_V + (size_t)c * LATDIM) + lane);
        float p = q.x * k4.x + q.y * k4.y + q.z * k4.z + q.w * k4.w;
        p += __shfl_xor_sync(0xffffffffu, p, 1);
        p += __shfl_xor_sync(0xffffffffu, p, 2);
        p += __shfl_xor_sync(0xffffffffu, p, 4);
        p = fminf(fmaxf(p, -10.f), 10.f);
        float e = __expf(p);
        denom += e;
        ax = fmaf(e, v4.x, ax);
        ay = fmaf(e, v4.y, ay);
        az = fmaf(e, v4.z, az);
        aw = fmaf(e, v4.w, aw);
    }

    float inv = 1.f / (denom + 1e-8f);
    float4 o = make_float4(ax * inv, ay * inv, az * inv, aw * inv);
    *((float4*)out + (size_t)warp * 32 + lane) = o;
}

// ============================================================
extern "C" void kernel_launch(void* const* d_in, const int* in_sizes, int n_in,
                              void* d_out, int out_size) {
    const float* E    = (const float*)d_in[0];
    const float* qW   = (const float*)d_in[1];
    const float* kW   = (const float*)d_in[2];
    const float* vW   = (const float*)d_in[3];
    const int*   rows = (const int*)d_in[4];
    const int*   cols = (const int*)d_in[5];

    int N  = in_sizes[0] / LATDIM;
    int Eg = in_sizes[4];

    int nb = (N + 1023) / 1024;

    // CSR front-half first; gemm3 stays the 4th launch so the ncu capture
    // slot profiles the GEMM again (verify fma% up / L1% down).
    zero_kernel<<<(N + 255) / 256, 256>>>(N);
    hist_kernel<<<(Eg + 255) / 256, 256>>>(rows, Eg);
    scan_pass1<<<nb, 1024>>>(N);

    dim3 gg((N + 127) / 128, 3);
    gemm3_kernel<<<gg, 256>>>(E, qW, kW, vW, N);

    scan_pass2<<<1, 32>>>(nb);
    scan_pass3<<<(N + 1024) / 1024, 1024>>>(N);   // covers i == N sentinel
    scatter_kernel<<<(Eg + 255) / 256, 256>>>(rows, cols, Eg);

    attn_kernel<<<(N + 7) / 8, 256>>>((float*)d_out, N);
}